// round 2
// baseline (speedup 1.0000x reference)
#include <cuda_runtime.h>
#include <cstdint>

#define DD 128          // feature dim
#define BM 64           // rows per tile
#define TM 4            // rows per thread
#define TN 8            // cols per thread
#define NTHREADS 256

// scratch: aggregated messages per node (N=50000 fixed for this problem)
__device__ float g_agg[50000 * 128];

// ---------------------------------------------------------------------------
// helpers
// ---------------------------------------------------------------------------
__device__ __forceinline__ void load_wtile(const float* __restrict__ W, float* sW, int tid) {
    // load a 32x128 fp32 weight tile (4096 floats) with 256 threads
    const float4* Wg = reinterpret_cast<const float4*>(W);
    float4* sW4 = reinterpret_cast<float4*>(sW);
#pragma unroll
    for (int j = 0; j < 4; ++j) sW4[tid + j * 256] = Wg[tid + j * 256];
}

// sOut[BM][out_stride] = relu(sIn[BM][K] @ W[K][128] + bias)
template <int K, int IN_STRIDE>
__device__ __forceinline__ void mlp_layer_relu(
    const float* __restrict__ W, const float* __restrict__ bias,
    const float* sIn, float* sW, float* sOut, int out_stride,
    int ty, int tx, int tid)
{
    float acc[TM][TN];
#pragma unroll
    for (int i = 0; i < TM; ++i)
#pragma unroll
        for (int j = 0; j < TN; ++j) acc[i][j] = 0.0f;

#pragma unroll 1
    for (int kt = 0; kt < K / 32; ++kt) {
        __syncthreads();
        load_wtile(W + kt * 32 * DD, sW, tid);
        __syncthreads();
#pragma unroll
        for (int k4 = 0; k4 < 8; ++k4) {
            float4 a4[TM];
#pragma unroll
            for (int i = 0; i < TM; ++i)
                a4[i] = *reinterpret_cast<const float4*>(sIn + (ty * TM + i) * IN_STRIDE + kt * 32 + k4 * 4);
#pragma unroll
            for (int kk = 0; kk < 4; ++kk) {
                const float4* br = reinterpret_cast<const float4*>(sW + (k4 * 4 + kk) * DD + tx * TN);
                float4 b0 = br[0], b1 = br[1];
                float bv[TN] = {b0.x, b0.y, b0.z, b0.w, b1.x, b1.y, b1.z, b1.w};
#pragma unroll
                for (int i = 0; i < TM; ++i) {
                    const float* ap = reinterpret_cast<const float*>(&a4[i]);
                    float av = ap[kk];
#pragma unroll
                    for (int j = 0; j < TN; ++j) acc[i][j] = fmaf(av, bv[j], acc[i][j]);
                }
            }
        }
    }
    float bb[TN];
#pragma unroll
    for (int j = 0; j < TN; ++j) bb[j] = bias[tx * TN + j];
#pragma unroll
    for (int i = 0; i < TM; ++i)
#pragma unroll
        for (int j = 0; j < TN; ++j)
            sOut[(ty * TM + i) * out_stride + tx * TN + j] = fmaxf(acc[i][j] + bb[j], 0.0f);
}

// last layer: acc = sIn[BM][128] @ W[128][128]  (no activation; epilogue by caller)
template <int IN_STRIDE>
__device__ __forceinline__ void mlp_layer_final(
    const float* __restrict__ W,
    const float* sIn, float* sW,
    float acc[TM][TN], int ty, int tx, int tid)
{
#pragma unroll
    for (int i = 0; i < TM; ++i)
#pragma unroll
        for (int j = 0; j < TN; ++j) acc[i][j] = 0.0f;

#pragma unroll 1
    for (int kt = 0; kt < 4; ++kt) {
        __syncthreads();
        load_wtile(W + kt * 32 * DD, sW, tid);
        __syncthreads();
#pragma unroll
        for (int k4 = 0; k4 < 8; ++k4) {
            float4 a4[TM];
#pragma unroll
            for (int i = 0; i < TM; ++i)
                a4[i] = *reinterpret_cast<const float4*>(sIn + (ty * TM + i) * IN_STRIDE + kt * 32 + k4 * 4);
#pragma unroll
            for (int kk = 0; kk < 4; ++kk) {
                const float4* br = reinterpret_cast<const float4*>(sW + (k4 * 4 + kk) * DD + tx * TN);
                float4 b0 = br[0], b1 = br[1];
                float bv[TN] = {b0.x, b0.y, b0.z, b0.w, b1.x, b1.y, b1.z, b1.w};
#pragma unroll
                for (int i = 0; i < TM; ++i) {
                    const float* ap = reinterpret_cast<const float*>(&a4[i]);
                    float av = ap[kk];
#pragma unroll
                    for (int j = 0; j < TN; ++j) acc[i][j] = fmaf(av, bv[j], acc[i][j]);
                }
            }
        }
    }
}

// ---------------------------------------------------------------------------
// edge kernel: edge MLP (384->128->128->128) + residual + scatter-add to g_agg
// smem layout (floats): sIn[64][388] | sH1[64][132] | sH2[64][132] | sW[32][128] | sSrc[64] sDst[64]
// ---------------------------------------------------------------------------
#define E_SIN_STRIDE 388
#define E_SIN_FLOATS (64 * 388)
#define E_SH_FLOATS  (64 * 132)
#define E_SW_FLOATS  (32 * 128)
#define EDGE_SMEM_BYTES ((E_SIN_FLOATS + 2 * E_SH_FLOATS + E_SW_FLOATS) * 4 + 128 * 4)

__global__ void __launch_bounds__(NTHREADS, 1) edge_kernel(
    const float* __restrict__ x, const float* __restrict__ edge_attr,
    const int* __restrict__ src, const int* __restrict__ dst,
    const float* __restrict__ ew1, const float* __restrict__ eb1,
    const float* __restrict__ ew2, const float* __restrict__ eb2,
    const float* __restrict__ ew3, const float* __restrict__ eb3,
    float* __restrict__ edge_out, int N, int E)
{
    extern __shared__ float smem[];
    float* sIn = smem;
    float* sH1 = sIn + E_SIN_FLOATS;
    float* sH2 = sH1 + E_SH_FLOATS;
    float* sW  = sH2 + E_SH_FLOATS;
    int* sSrc = reinterpret_cast<int*>(sW + E_SW_FLOATS);
    int* sDst = sSrc + 64;

    const int tid = threadIdx.x;
    const int ty = tid >> 4, tx = tid & 15;
    const int e0 = blockIdx.x * BM;

    if (tid < BM) {
        int e = e0 + tid;
        int ec = (e < E) ? e : (E - 1);
        sSrc[tid] = src[ec];
        sDst[tid] = dst[ec];
    }
    __syncthreads();

    // gather [x[src] | x[dst] | edge_attr] into sIn (64 x 384, padded stride 388)
#pragma unroll
    for (int j = 0; j < 8; ++j) {
        int idx = tid + j * 256;        // 0..2047
        int row = idx >> 5;
        int c4  = idx & 31;
        int e = e0 + row;
        int ec = (e < E) ? e : (E - 1);
        float4 vs = reinterpret_cast<const float4*>(x + (size_t)sSrc[row] * DD)[c4];
        float4 vd = reinterpret_cast<const float4*>(x + (size_t)sDst[row] * DD)[c4];
        float4 va = reinterpret_cast<const float4*>(edge_attr + (size_t)ec * DD)[c4];
        float4* base = reinterpret_cast<float4*>(sIn + row * E_SIN_STRIDE);
        base[c4] = vs;
        reinterpret_cast<float4*>(sIn + row * E_SIN_STRIDE + DD)[c4] = vd;
        reinterpret_cast<float4*>(sIn + row * E_SIN_STRIDE + 2 * DD)[c4] = va;
    }
    __syncthreads();

    mlp_layer_relu<384, E_SIN_STRIDE>(ew1, eb1, sIn, sW, sH1, 132, ty, tx, tid);
    mlp_layer_relu<128, 132>(ew2, eb2, sH1, sW, sH2, 132, ty, tx, tid);

    float acc[TM][TN];
    mlp_layer_final<132>(ew3, sH2, sW, acc, ty, tx, tid);

    float bb[TN];
#pragma unroll
    for (int j = 0; j < TN; ++j) bb[j] = eb3[tx * TN + j];

#pragma unroll
    for (int i = 0; i < TM; ++i) {
        int r = ty * TM + i;
        int e = e0 + r;
        if (e < E) {
            float v[TN];
#pragma unroll
            for (int j = 0; j < TN; ++j)
                v[j] = acc[i][j] + bb[j] + sIn[r * E_SIN_STRIDE + 2 * DD + tx * TN + j];
            float4 v0 = make_float4(v[0], v[1], v[2], v[3]);
            float4 v1 = make_float4(v[4], v[5], v[6], v[7]);
            float4* op = reinterpret_cast<float4*>(edge_out + (size_t)e * DD + tx * TN);
            op[0] = v0; op[1] = v1;
            float4* ap = reinterpret_cast<float4*>(g_agg + (size_t)sDst[r] * DD + tx * TN);
            atomicAdd(ap, v0);
            atomicAdd(ap + 1, v1);
        }
    }
}

// ---------------------------------------------------------------------------
// node kernel: node MLP (256->128->128->128) + residual
// smem: sIn[64][260] | sH1[64][132] | sH2[64][132] | sW[32][128]
// ---------------------------------------------------------------------------
#define N_SIN_STRIDE 260
#define N_SIN_FLOATS (64 * 260)
#define NODE_SMEM_BYTES ((N_SIN_FLOATS + 2 * E_SH_FLOATS + E_SW_FLOATS) * 4)

__global__ void __launch_bounds__(NTHREADS, 1) node_kernel(
    const float* __restrict__ x,
    const float* __restrict__ nw1, const float* __restrict__ nb1,
    const float* __restrict__ nw2, const float* __restrict__ nb2,
    const float* __restrict__ nw3, const float* __restrict__ nb3,
    float* __restrict__ x_out, int N)
{
    extern __shared__ float smem[];
    float* sIn = smem;
    float* sH1 = sIn + N_SIN_FLOATS;
    float* sH2 = sH1 + E_SH_FLOATS;
    float* sW  = sH2 + E_SH_FLOATS;

    const int tid = threadIdx.x;
    const int ty = tid >> 4, tx = tid & 15;
    const int n0 = blockIdx.x * BM;

#pragma unroll
    for (int j = 0; j < 8; ++j) {
        int idx = tid + j * 256;
        int row = idx >> 5;
        int c4  = idx & 31;
        int n = n0 + row;
        int nc = (n < N) ? n : (N - 1);
        float4 vx = reinterpret_cast<const float4*>(x + (size_t)nc * DD)[c4];
        float4 va = reinterpret_cast<const float4*>(g_agg + (size_t)nc * DD)[c4];
        reinterpret_cast<float4*>(sIn + row * N_SIN_STRIDE)[c4] = vx;
        reinterpret_cast<float4*>(sIn + row * N_SIN_STRIDE + DD)[c4] = va;
    }
    __syncthreads();

    mlp_layer_relu<256, N_SIN_STRIDE>(nw1, nb1, sIn, sW, sH1, 132, ty, tx, tid);
    mlp_layer_relu<128, 132>(nw2, nb2, sH1, sW, sH2, 132, ty, tx, tid);

    float acc[TM][TN];
    mlp_layer_final<132>(nw3, sH2, sW, acc, ty, tx, tid);

    float bb[TN];
#pragma unroll
    for (int j = 0; j < TN; ++j) bb[j] = nb3[tx * TN + j];

#pragma unroll
    for (int i = 0; i < TM; ++i) {
        int r = ty * TM + i;
        int n = n0 + r;
        if (n < N) {
            float v[TN];
#pragma unroll
            for (int j = 0; j < TN; ++j)
                v[j] = acc[i][j] + bb[j] + sIn[r * N_SIN_STRIDE + tx * TN + j];  // residual x
            float4 v0 = make_float4(v[0], v[1], v[2], v[3]);
            float4 v1 = make_float4(v[4], v[5], v[6], v[7]);
            float4* op = reinterpret_cast<float4*>(x_out + (size_t)n * DD + tx * TN);
            op[0] = v0; op[1] = v1;
        }
    }
}

__global__ void zero_agg_kernel(int n4) {
    float4* p = reinterpret_cast<float4*>(g_agg);
    for (int i = blockIdx.x * blockDim.x + threadIdx.x; i < n4; i += gridDim.x * blockDim.x)
        p[i] = make_float4(0.f, 0.f, 0.f, 0.f);
}

// ---------------------------------------------------------------------------
extern "C" void kernel_launch(void* const* d_in, const int* in_sizes, int n_in,
                              void* d_out, int out_size)
{
    const float* x         = (const float*)d_in[0];
    const float* edge_attr = (const float*)d_in[1];
    const int*   ei        = (const int*)d_in[2];
    const float* ew1 = (const float*)d_in[3];
    const float* eb1 = (const float*)d_in[4];
    const float* ew2 = (const float*)d_in[5];
    const float* eb2 = (const float*)d_in[6];
    const float* ew3 = (const float*)d_in[7];
    const float* eb3 = (const float*)d_in[8];
    const float* nw1 = (const float*)d_in[9];
    const float* nb1 = (const float*)d_in[10];
    const float* nw2 = (const float*)d_in[11];
    const float* nb2 = (const float*)d_in[12];
    const float* nw3 = (const float*)d_in[13];
    const float* nb3 = (const float*)d_in[14];

    int N = in_sizes[0] / DD;
    int E = in_sizes[1] / DD;
    const int* src = ei;
    const int* dst = ei + E;

    float* x_new    = (float*)d_out;                      // [N, D]
    float* edge_new = (float*)d_out + (size_t)N * DD;     // [E, D]

    cudaFuncSetAttribute(edge_kernel, cudaFuncAttributeMaxDynamicSharedMemorySize, EDGE_SMEM_BYTES);
    cudaFuncSetAttribute(node_kernel, cudaFuncAttributeMaxDynamicSharedMemorySize, NODE_SMEM_BYTES);

    zero_agg_kernel<<<256, 256>>>(N * DD / 4);
    edge_kernel<<<(E + BM - 1) / BM, NTHREADS, EDGE_SMEM_BYTES>>>(
        x, edge_attr, src, dst, ew1, eb1, ew2, eb2, ew3, eb3, edge_new, N, E);
    node_kernel<<<(N + BM - 1) / BM, NTHREADS, NODE_SMEM_BYTES>>>(
        x, nw1, nb1, nw2, nb2, nw3, nb3, x_new, N);
}

// round 5
// speedup vs baseline: 1.7665x; 1.7665x over previous
#include <cuda_runtime.h>
#include <mma.h>
#include <cstdint>

using namespace nvcuda;

#define NT 256
#define ROWS 256         // rows per CTA
#define LDA 132          // smem leading dim (floats)

// scratch: aggregated messages per node (N=50000, D=128 fixed)
__device__ float g_agg[50000 * 128];

using FragA = wmma::fragment<wmma::matrix_a, 16, 16, 8, wmma::precision::tf32, wmma::row_major>;
using FragB = wmma::fragment<wmma::matrix_b, 16, 16, 8, wmma::precision::tf32, wmma::row_major>;
using FragC = wmma::fragment<wmma::accumulator, 16, 16, 8, float>;

// ---------------------------------------------------------------------------
// load 32 k-rows of W[K,128] (row-major) into sB [32][LDA]
// ---------------------------------------------------------------------------
__device__ __forceinline__ void load_btile(const float* __restrict__ W, float* sB, int tid) {
#pragma unroll
    for (int i = tid; i < 32 * 32; i += NT) {
        int row = i >> 5, c4 = i & 31;
        *(float4*)(sB + row * LDA + c4 * 4) = ((const float4*)(W + (size_t)row * 128))[c4];
    }
}

// one 32-wide k-tile of the GEMM: acc += A[.., 32] @ B[32, 128]
__device__ __forceinline__ void do_ktile(const float* sA, const float* sB,
                                         FragC (&c)[4][4], int wm, int wn) {
#pragma unroll
    for (int ks = 0; ks < 4; ++ks) {
        FragA a[4];
        FragB b[4];
#pragma unroll
        for (int im = 0; im < 4; ++im) {
            wmma::load_matrix_sync(a[im], sA + (wm * 64 + im * 16) * LDA + ks * 8, LDA);
#pragma unroll
            for (int e = 0; e < a[im].num_elements; ++e)
                a[im].x[e] = wmma::__float_to_tf32(a[im].x[e]);
        }
#pragma unroll
        for (int in = 0; in < 4; ++in) {
            wmma::load_matrix_sync(b[in], sB + ks * 8 * LDA + wn * 64 + in * 16, LDA);
#pragma unroll
            for (int e = 0; e < b[in].num_elements; ++e)
                b[in].x[e] = wmma::__float_to_tf32(b[in].x[e]);
        }
#pragma unroll
        for (int im = 0; im < 4; ++im)
#pragma unroll
            for (int in = 0; in < 4; ++in)
                wmma::mma_sync(c[im][in], a[im], b[in], c[im][in]);
    }
}

// K=128 GEMM chunk from sA (all 4 k-tiles), streaming B from W
__device__ __forceinline__ void gemm128(const float* __restrict__ W, const float* sA, float* sB,
                                        FragC (&c)[4][4], int wm, int wn, int tid) {
#pragma unroll 1
    for (int kt = 0; kt < 4; ++kt) {
        __syncthreads();
        load_btile(W + (size_t)kt * 32 * 128, sB, tid);
        __syncthreads();
        do_ktile(sA + kt * 32, sB, c, wm, wn);
    }
}

// store accumulators to sOut, then (bias [+relu]) elementwise in smem
__device__ __forceinline__ void store_frags(float* sOut, FragC (&c)[4][4], int wm, int wn) {
#pragma unroll
    for (int im = 0; im < 4; ++im)
#pragma unroll
        for (int in = 0; in < 4; ++in)
            wmma::store_matrix_sync(sOut + (wm * 64 + im * 16) * LDA + wn * 64 + in * 16,
                                    c[im][in], LDA, wmma::mem_row_major);
}

__device__ __forceinline__ void bias_relu_inplace(float* sA, const float* __restrict__ bias, int tid) {
#pragma unroll 1
    for (int i = tid; i < ROWS * 32; i += NT) {
        int row = i >> 5, c4 = i & 31;
        float4 b4 = ((const float4*)bias)[c4];
        float4* p = (float4*)(sA + row * LDA + c4 * 4);
        float4 v = *p;
        v.x = fmaxf(v.x + b4.x, 0.f); v.y = fmaxf(v.y + b4.y, 0.f);
        v.z = fmaxf(v.z + b4.z, 0.f); v.w = fmaxf(v.w + b4.w, 0.f);
        *p = v;
    }
}

// ---------------------------------------------------------------------------
// edge kernel: 256 edges/CTA. MLP 384->128->128->128 + residual + scatter-add.
// smem: sA [256][132] | sB [32][132] | sSrc[256] | sDst[256]
// ---------------------------------------------------------------------------
#define SA_FLOATS (ROWS * LDA)
#define SB_FLOATS (32 * LDA)
#define SMEM_BYTES ((SA_FLOATS + SB_FLOATS) * 4 + 2 * ROWS * 4)

__global__ void __launch_bounds__(NT, 1) edge_kernel_mma(
    const float* __restrict__ x, const float* __restrict__ edge_attr,
    const int* __restrict__ src, const int* __restrict__ dst,
    const float* __restrict__ ew1, const float* __restrict__ eb1,
    const float* __restrict__ ew2, const float* __restrict__ eb2,
    const float* __restrict__ ew3, const float* __restrict__ eb3,
    float* __restrict__ edge_out, int E)
{
    extern __shared__ float smem[];
    float* sA = smem;
    float* sB = sA + SA_FLOATS;
    int* sSrc = (int*)(sB + SB_FLOATS);
    int* sDst = sSrc + ROWS;

    const int tid = threadIdx.x;
    const int wid = tid >> 5;
    const int wm = wid >> 1, wn = wid & 1;
    const int e0 = blockIdx.x * ROWS;

    if (tid < ROWS) {
        int e = e0 + tid; if (e >= E) e = E - 1;
        sSrc[tid] = src[e];
        sDst[tid] = dst[e];
    }

    FragC c[4][4];
#pragma unroll
    for (int im = 0; im < 4; ++im)
#pragma unroll
        for (int in = 0; in < 4; ++in) wmma::fill_fragment(c[im][in], 0.0f);

    // ---- layer 1: K=384 in 3 gathered chunks ----
#pragma unroll 1
    for (int ch = 0; ch < 3; ++ch) {
        __syncthreads();
#pragma unroll 1
        for (int i = tid; i < ROWS * 32; i += NT) {
            int row = i >> 5, c4 = i & 31;
            const float* sp;
            if (ch == 0)      sp = x + (size_t)sSrc[row] * 128;
            else if (ch == 1) sp = x + (size_t)sDst[row] * 128;
            else { int e = e0 + row; if (e >= E) e = E - 1; sp = edge_attr + (size_t)e * 128; }
            *(float4*)(sA + row * LDA + c4 * 4) = ((const float4*)sp)[c4];
        }
        gemm128(ew1 + (size_t)ch * 128 * 128, sA, sB, c, wm, wn, tid);
    }
    __syncthreads();
    store_frags(sA, c, wm, wn);
    __syncthreads();
    bias_relu_inplace(sA, eb1, tid);

    // ---- layer 2 ----
#pragma unroll
    for (int im = 0; im < 4; ++im)
#pragma unroll
        for (int in = 0; in < 4; ++in) wmma::fill_fragment(c[im][in], 0.0f);
    gemm128(ew2, sA, sB, c, wm, wn, tid);
    __syncthreads();
    store_frags(sA, c, wm, wn);
    __syncthreads();
    bias_relu_inplace(sA, eb2, tid);

    // ---- layer 3 ----
#pragma unroll
    for (int im = 0; im < 4; ++im)
#pragma unroll
        for (int in = 0; in < 4; ++in) wmma::fill_fragment(c[im][in], 0.0f);
    gemm128(ew3, sA, sB, c, wm, wn, tid);
    __syncthreads();
    store_frags(sA, c, wm, wn);
    __syncthreads();

    // ---- epilogue: + eb3 + edge_attr residual; store; scatter-add ----
#pragma unroll 1
    for (int i = tid; i < ROWS * 32; i += NT) {
        int row = i >> 5, c4 = i & 31;
        int e = e0 + row;
        if (e < E) {
            float4 b4 = ((const float4*)eb3)[c4];
            float4 m = *(float4*)(sA + row * LDA + c4 * 4);
            float4 a = ((const float4*)(edge_attr + (size_t)e * 128))[c4];
            float4 v = make_float4(m.x + b4.x + a.x, m.y + b4.y + a.y,
                                   m.z + b4.z + a.z, m.w + b4.w + a.w);
            ((float4*)(edge_out + (size_t)e * 128))[c4] = v;
            atomicAdd((float4*)(g_agg + (size_t)sDst[row] * 128 + c4 * 4), v);
        }
    }
}

// ---------------------------------------------------------------------------
// node kernel: 256 nodes/CTA. MLP 256->128->128->128 + residual.
// ---------------------------------------------------------------------------
__global__ void __launch_bounds__(NT, 1) node_kernel_mma(
    const float* __restrict__ x,
    const float* __restrict__ nw1, const float* __restrict__ nb1,
    const float* __restrict__ nw2, const float* __restrict__ nb2,
    const float* __restrict__ nw3, const float* __restrict__ nb3,
    float* __restrict__ x_out, int N)
{
    extern __shared__ float smem[];
    float* sA = smem;
    float* sB = sA + SA_FLOATS;

    const int tid = threadIdx.x;
    const int wid = tid >> 5;
    const int wm = wid >> 1, wn = wid & 1;
    const int n0 = blockIdx.x * ROWS;

    FragC c[4][4];
#pragma unroll
    for (int im = 0; im < 4; ++im)
#pragma unroll
        for (int in = 0; in < 4; ++in) wmma::fill_fragment(c[im][in], 0.0f);

    // ---- layer 1: K=256 in 2 chunks (x | agg) ----
#pragma unroll 1
    for (int ch = 0; ch < 2; ++ch) {
        __syncthreads();
#pragma unroll 1
        for (int i = tid; i < ROWS * 32; i += NT) {
            int row = i >> 5, c4 = i & 31;
            int n = n0 + row; if (n >= N) n = N - 1;
            const float* sp = (ch == 0) ? (x + (size_t)n * 128) : (g_agg + (size_t)n * 128);
            *(float4*)(sA + row * LDA + c4 * 4) = ((const float4*)sp)[c4];
        }
        gemm128(nw1 + (size_t)ch * 128 * 128, sA, sB, c, wm, wn, tid);
    }
    __syncthreads();
    store_frags(sA, c, wm, wn);
    __syncthreads();
    bias_relu_inplace(sA, nb1, tid);

    // ---- layer 2 ----
#pragma unroll
    for (int im = 0; im < 4; ++im)
#pragma unroll
        for (int in = 0; in < 4; ++in) wmma::fill_fragment(c[im][in], 0.0f);
    gemm128(nw2, sA, sB, c, wm, wn, tid);
    __syncthreads();
    store_frags(sA, c, wm, wn);
    __syncthreads();
    bias_relu_inplace(sA, nb2, tid);

    // ---- layer 3 ----
#pragma unroll
    for (int im = 0; im < 4; ++im)
#pragma unroll
        for (int in = 0; in < 4; ++in) wmma::fill_fragment(c[im][in], 0.0f);
    gemm128(nw3, sA, sB, c, wm, wn, tid);
    __syncthreads();
    store_frags(sA, c, wm, wn);
    __syncthreads();

    // ---- epilogue: + nb3 + x residual; store ----
#pragma unroll 1
    for (int i = tid; i < ROWS * 32; i += NT) {
        int row = i >> 5, c4 = i & 31;
        int n = n0 + row;
        if (n < N) {
            float4 b4 = ((const float4*)nb3)[c4];
            float4 m = *(float4*)(sA + row * LDA + c4 * 4);
            float4 a = ((const float4*)(x + (size_t)n * 128))[c4];
            ((float4*)(x_out + (size_t)n * 128))[c4] =
                make_float4(m.x + b4.x + a.x, m.y + b4.y + a.y,
                            m.z + b4.z + a.z, m.w + b4.w + a.w);
        }
    }
}

__global__ void zero_agg_kernel(int n4) {
    float4* p = reinterpret_cast<float4*>(g_agg);
    for (int i = blockIdx.x * blockDim.x + threadIdx.x; i < n4; i += gridDim.x * blockDim.x)
        p[i] = make_float4(0.f, 0.f, 0.f, 0.f);
}

// ---------------------------------------------------------------------------
extern "C" void kernel_launch(void* const* d_in, const int* in_sizes, int n_in,
                              void* d_out, int out_size)
{
    const float* x         = (const float*)d_in[0];
    const float* edge_attr = (const float*)d_in[1];
    const int*   ei        = (const int*)d_in[2];
    const float* ew1 = (const float*)d_in[3];
    const float* eb1 = (const float*)d_in[4];
    const float* ew2 = (const float*)d_in[5];
    const float* eb2 = (const float*)d_in[6];
    const float* ew3 = (const float*)d_in[7];
    const float* eb3 = (const float*)d_in[8];
    const float* nw1 = (const float*)d_in[9];
    const float* nb1 = (const float*)d_in[10];
    const float* nw2 = (const float*)d_in[11];
    const float* nb2 = (const float*)d_in[12];
    const float* nw3 = (const float*)d_in[13];
    const float* nb3 = (const float*)d_in[14];

    int N = in_sizes[0] / 128;
    int E = in_sizes[1] / 128;
    const int* src = ei;
    const int* dst = ei + E;

    float* x_new    = (float*)d_out;
    float* edge_new = (float*)d_out + (size_t)N * 128;

    cudaFuncSetAttribute(edge_kernel_mma, cudaFuncAttributeMaxDynamicSharedMemorySize, SMEM_BYTES);
    cudaFuncSetAttribute(node_kernel_mma, cudaFuncAttributeMaxDynamicSharedMemorySize, SMEM_BYTES);

    zero_agg_kernel<<<256, 256>>>(N * 128 / 4);
    edge_kernel_mma<<<(E + ROWS - 1) / ROWS, NT, SMEM_BYTES>>>(
        x, edge_attr, src, dst, ew1, eb1, ew2, eb2, ew3, eb3, edge_new, E);
    node_kernel_mma<<<(N + ROWS - 1) / ROWS, NT, SMEM_BYTES>>>(
        x, nw1, nb1, nw2, nb2, nw3, nb3, x_new, N);
}